// round 15
// baseline (speedup 1.0000x reference)
#include <cuda_runtime.h>
#include <cuda_fp16.h>

#define NA   8
#define BSZ  4
#define THW  1024
#define DD   512
#define DA   64
#define NROWS (BSZ*THW)   // 4096
#define NQKV (3*NA*DA)    // 1536
#define STG  32768        // GEMM stage: A 16K | B 16K  (128x128 tile)
#define ASTG 24576        // attn stage: K 4K | V 4K | Bias 16K
#define LOG2E 1.44269504f

// ---------------- device scratch (allocation forbidden) ----------------
__device__ __half g_x [NROWS*DD];                // normalized x, fp16
__device__ __half g_q [NA*NROWS*DA];             // q (pre-scaled log2e/8)
__device__ __half g_k [NA*NROWS*DA];
__device__ __half g_v [NA*NROWS*DA];
__device__ __half g_ao[NROWS*DD];                // concat attn out
__device__ __half g_wt[NQKV*DD];                 // qkv weights [n][d]
__device__ __half g_wp[DD*DD];                   // proj weights [o][i]
__device__ unsigned g_mb[THW*32];                // mask bitpack [q][kword]
__device__ float g_pO[2][NROWS*DD];              // split-KV partial O (unnormalized)
__device__ float g_pml[2][NA][NROWS][2];         // split-KV partial {m, l}

// ---------------- helpers ----------------
__device__ __forceinline__ void mma4(float c[4], const unsigned a[4], unsigned b0, unsigned b1) {
    asm volatile(
        "mma.sync.aligned.m16n8k16.row.col.f32.f16.f16.f32 "
        "{%0,%1,%2,%3}, {%4,%5,%6,%7}, {%8,%9}, {%0,%1,%2,%3};\n"
        : "+f"(c[0]), "+f"(c[1]), "+f"(c[2]), "+f"(c[3])
        : "r"(a[0]), "r"(a[1]), "r"(a[2]), "r"(a[3]), "r"(b0), "r"(b1));
}

__device__ __forceinline__ void ldsm4(unsigned& r0, unsigned& r1, unsigned& r2, unsigned& r3,
                                      const void* p) {
    unsigned addr = (unsigned)__cvta_generic_to_shared(p);
    asm volatile("ldmatrix.sync.aligned.m8n8.x4.shared.b16 {%0,%1,%2,%3}, [%4];"
                 : "=r"(r0), "=r"(r1), "=r"(r2), "=r"(r3) : "r"(addr));
}

__device__ __forceinline__ void ldsm4t(unsigned& r0, unsigned& r1, unsigned& r2, unsigned& r3,
                                       const void* p) {
    unsigned addr = (unsigned)__cvta_generic_to_shared(p);
    asm volatile("ldmatrix.sync.aligned.m8n8.x4.trans.shared.b16 {%0,%1,%2,%3}, [%4];"
                 : "=r"(r0), "=r"(r1), "=r"(r2), "=r"(r3) : "r"(addr));
}

__device__ __forceinline__ void cpa16(void* dst, const void* src) {
    unsigned d = (unsigned)__cvta_generic_to_shared(dst);
    asm volatile("cp.async.cg.shared.global [%0], [%1], 16;" :: "r"(d), "l"(src));
}
__device__ __forceinline__ void cp_commit() {
    asm volatile("cp.async.commit_group;" ::: "memory");
}
template<int N> __device__ __forceinline__ void cp_wait() {
    asm volatile("cp.async.wait_group %0;" :: "n"(N) : "memory");
}

__device__ __forceinline__ unsigned pack2(float a, float b) {
    __half2 h2; h2.x = __float2half_rn(a); h2.y = __float2half_rn(b);
    return *reinterpret_cast<unsigned*>(&h2);
}

__device__ __forceinline__ float ex2f(float x) {
    float r;
    asm("ex2.approx.f32 %0, %1;" : "=f"(r) : "f"(x));
    return r;
}

// ---------------------------------------------------------------- LayerNorm
__global__ void ln_kernel(const float* __restrict__ x,
                          const float* __restrict__ gamma,
                          const float* __restrict__ beta) {
    int row = blockIdx.x;
    int t   = threadIdx.x;              // 128 threads
    const float* xr = x + (size_t)row * DD;
    float v[4];
    float s = 0.f;
#pragma unroll
    for (int i = 0; i < 4; i++) { v[i] = xr[i * 128 + t]; s += v[i]; }

    __shared__ float rbuf[4];
    __shared__ float stat;
#pragma unroll
    for (int o = 16; o > 0; o >>= 1) s += __shfl_xor_sync(0xffffffffu, s, o);
    if ((t & 31) == 0) rbuf[t >> 5] = s;
    __syncthreads();
    if (t == 0) stat = rbuf[0] + rbuf[1] + rbuf[2] + rbuf[3];
    __syncthreads();
    float mean = stat * (1.f / DD);

    float ss = 0.f;
#pragma unroll
    for (int i = 0; i < 4; i++) { float d = v[i] - mean; ss += d * d; }
    __syncthreads();
#pragma unroll
    for (int o = 16; o > 0; o >>= 1) ss += __shfl_xor_sync(0xffffffffu, ss, o);
    if ((t & 31) == 0) rbuf[t >> 5] = ss;
    __syncthreads();
    if (t == 0) stat = rbuf[0] + rbuf[1] + rbuf[2] + rbuf[3];
    __syncthreads();
    float rstd = rsqrtf(stat * (1.f / DD) + 1e-5f);

#pragma unroll
    for (int i = 0; i < 4; i++) {
        int c = i * 128 + t;
        float y = (v[i] - mean) * rstd * gamma[c] + beta[c];
        g_x[(size_t)row * DD + c] = __float2half_rn(y);
    }
}

// ------------------------------------------------- unified prep kernel
#define PW_BLKS 192
#define PWP_BLKS 32
__global__ void prep_all(const float* __restrict__ wq,
                         const float* __restrict__ wk,
                         const float* __restrict__ wv,
                         const float* __restrict__ wp,
                         const int* __restrict__ M) {
    int bx = blockIdx.x;
    if (bx < PW_BLKS) {
        __shared__ float tile[64][65];
        int wh = bx >> 3;                 // 0..23
        int which = wh >> 3, h = wh & 7;
        const float* w = ((which == 0) ? wq : (which == 1) ? wk : wv) + (size_t)h * DD * DA;
        int n0 = which * 512 + h * 64;
        int d0 = (bx & 7) * 64;
#pragma unroll
        for (int it = 0; it < 16; it++) {
            int idx = it * 256 + threadIdx.x;    // 4096
            int r = idx >> 6, e = idx & 63;
            tile[r][e] = w[(size_t)(d0 + r) * DA + e];
        }
        __syncthreads();
#pragma unroll
        for (int it = 0; it < 8; it++) {
            int idx = it * 256 + threadIdx.x;    // 2048
            int e = idx >> 5, j = idx & 31;
            *(unsigned*)(g_wt + (size_t)(n0 + e) * DD + d0 + 2 * j) =
                pack2(tile[2 * j][e], tile[2 * j + 1][e]);
        }
    } else if (bx < PW_BLKS + PWP_BLKS) {
        int base = (bx - PW_BLKS) * 256 + threadIdx.x;   // 8192 threads
#pragma unroll
        for (int i = 0; i < 16; i++) {
            int p = base + i * 8192;                     // 131072 float2 total
            float2 v = ((const float2*)wp)[p];
            ((unsigned*)g_wp)[p] = pack2(v.x, v.y);
        }
    } else {
        int w = (bx - PW_BLKS - PWP_BLKS) * 8 + (threadIdx.x >> 5);  // 32768 words
        int lane = threadIdx.x & 31;
        unsigned bits = __ballot_sync(0xffffffffu, M[(size_t)w * 32 + lane] != 0);
        if (lane == 0) g_mb[w] = bits;
    }
}

// ---------------------------------------------------------------- big GEMM
// C[128m x 128n] per block, 8 warps (4m x 2n), warp tile 32x64, k-tile 64.
struct GemmAcc { float c[2][8][4]; };

__device__ __forceinline__ void gemm_stage_load(
    const __half* Asrc, const __half* Bsrc, char* S, int tid, int k0)
{
#pragma unroll
    for (int it = 0; it < 4; it++) {
        int flat = it * 256 + tid;
        int r = flat >> 3, cc = flat & 7;
        size_t so = (size_t)r * DD + k0 + cc * 8;
        int off = r * 128 + ((cc ^ (r & 7)) << 4);
        cpa16(S + off,         Asrc + so);
        cpa16(S + 16384 + off, Bsrc + so);
    }
    cp_commit();
}

__device__ __forceinline__ void gemm_stage_compute(
    char* S, int mw, int nw, int grp, int li, GemmAcc& acc)
{
    char* As = S;
    char* Bs = S + 16384;
#pragma unroll
    for (int s4 = 0; s4 < 4; s4++) {
        unsigned af[2][4];
#pragma unroll
        for (int mi = 0; mi < 2; mi++) {
            int ar = mw + mi * 16 + ((grp & 1) << 3) + li;
            int sw = (((s4 * 2 + (grp >> 1)) ^ (ar & 7)) << 4);
            ldsm4(af[mi][0], af[mi][1], af[mi][2], af[mi][3], As + ar * 128 + sw);
        }
        unsigned bf[4][4];
#pragma unroll
        for (int jp = 0; jp < 4; jp++) {
            int br = nw + jp * 16 + ((grp >> 1) << 3) + li;
            int sw = (((s4 * 2 + (grp & 1)) ^ (br & 7)) << 4);
            ldsm4(bf[jp][0], bf[jp][1], bf[jp][2], bf[jp][3], Bs + br * 128 + sw);
        }
#pragma unroll
        for (int mi = 0; mi < 2; mi++)
#pragma unroll
            for (int jp = 0; jp < 4; jp++) {
                mma4(acc.c[mi][jp * 2],     af[mi], bf[jp][0], bf[jp][1]);
                mma4(acc.c[mi][jp * 2 + 1], af[mi], bf[jp][2], bf[jp][3]);
            }
    }
}

__device__ __forceinline__ void gemm_mainloop(
    const __half* Asrc, const __half* Bsrc,
    char* sm, int tid, int mw, int nw, int grp, int li, GemmAcc& acc)
{
    const int NK = DD / 64;   // 8
    gemm_stage_load(Asrc, Bsrc, sm,       tid, 0);
    gemm_stage_load(Asrc, Bsrc, sm + STG, tid, 64);
#pragma unroll 1
    for (int kt = 0; kt < NK; kt++) {
        if (kt + 2 < NK) {
            gemm_stage_load(Asrc, Bsrc, sm + ((kt + 2) % 3) * STG, tid, (kt + 2) * 64);
            cp_wait<2>();
        } else if (kt + 1 < NK) {
            cp_wait<1>();
        } else {
            cp_wait<0>();
        }
        __syncthreads();
        gemm_stage_compute(sm + (kt % 3) * STG, mw, nw, grp, li, acc);
        __syncthreads();
    }
}

// qkv GEMM: grid (32, 12), 256 thr, dynamic smem 96KB
__global__ __launch_bounds__(256, 2) void qkv_g() {
    extern __shared__ __align__(16) char smd[];
    int m0 = blockIdx.x * 128, n0 = blockIdx.y * 128;

    int tid = threadIdx.x, lane = tid & 31, wid = tid >> 5;
    int g = lane >> 2, tg = lane & 3, grp = lane >> 3, li = lane & 7;
    int mw = (wid >> 1) * 32, nw = (wid & 1) * 64;

    GemmAcc acc = {};
    gemm_mainloop(g_x + (size_t)m0 * DD, g_wt + (size_t)n0 * DD,
                  smd, tid, mw, nw, grp, li, acc);

    int col0 = n0 + nw;                       // 64-aligned; constant per warp
    int which = col0 >> 9;
    int h = (col0 >> 6) & 7;
    float scale = (which == 0) ? 0.125f * LOG2E : 1.0f;   // q folded into log2 domain
    __half* o = (which == 0) ? g_q : ((which == 1) ? g_k : g_v);
#pragma unroll
    for (int mi = 0; mi < 2; mi++)
#pragma unroll
        for (int nj = 0; nj < 8; nj++) {
            int m = m0 + mw + mi * 16 + g;
            int e = nj * 8 + 2 * tg;
            size_t b0 = ((size_t)(h * NROWS + m)) * DA + e;
            size_t b1 = ((size_t)(h * NROWS + m + 8)) * DA + e;
            *(unsigned*)(o + b0) = pack2(acc.c[mi][nj][0] * scale, acc.c[mi][nj][1] * scale);
            *(unsigned*)(o + b1) = pack2(acc.c[mi][nj][2] * scale, acc.c[mi][nj][3] * scale);
        }
}

// proj GEMM + residual: grid (32, 4), 256 thr, dynamic smem 96KB
__global__ __launch_bounds__(256, 2) void proj_g(const float* __restrict__ x,
                                                 float* __restrict__ out) {
    extern __shared__ __align__(16) char smd[];
    int m0 = blockIdx.x * 128, n0 = blockIdx.y * 128;

    int tid = threadIdx.x, lane = tid & 31, wid = tid >> 5;
    int g = lane >> 2, tg = lane & 3, grp = lane >> 3, li = lane & 7;
    int mw = (wid >> 1) * 32, nw = (wid & 1) * 64;

    GemmAcc acc = {};
    gemm_mainloop(g_ao + (size_t)m0 * DD, g_wp + (size_t)n0 * DD,
                  smd, tid, mw, nw, grp, li, acc);

#pragma unroll
    for (int mi = 0; mi < 2; mi++)
#pragma unroll
        for (int nj = 0; nj < 8; nj++) {
            int m = m0 + mw + mi * 16 + g;
            int n = n0 + nw + nj * 8 + 2 * tg;
#pragma unroll
            for (int rr = 0; rr < 2; rr++) {
                size_t off = (size_t)(m + rr * 8) * DD + n;
                float2 xr = *(const float2*)&x[off];
                float2 r;
                r.x = acc.c[mi][nj][rr * 2 + 0] + xr.x;
                r.y = acc.c[mi][nj][rr * 2 + 1] + xr.y;
                *(float2*)&out[off] = r;
            }
        }
}

// ---------------------------------------------------------------- fused attention
// grid (8, 32, 2): q-tile 128 x (head,batch) x k-split. 256 threads.
// Each block handles 16 k-tiles of 32 tokens; partial (O, m, l) to scratch.
// All scores in log2 domain (q pre-scaled; bias FMA by LOG2E; mask -> -14427).
__global__ __launch_bounds__(256) void attn_kernel(const float* __restrict__ Bb) {
    __shared__ __align__(16) char sm[2][ASTG];

    int hb = blockIdx.y;
    int h = hb >> 2, b = hb & 3;
    int qr0 = blockIdx.x * 128;
    int ks = blockIdx.z;
    int kt0 = ks * 16;

    int tid = threadIdx.x, lane = tid & 31, wid = tid >> 5;
    int g = lane >> 2, tg = lane & 3, grp = lane >> 3, li = lane & 7;
    int mw = wid * 16;

    size_t kv = (size_t)(h * NROWS + b * THW) * DA;
    const float* Bblk = Bb + ((size_t)hb * THW + qr0) * THW;

    // ---- Q tile into sm[0], extract frags ----
#pragma unroll
    for (int it = 0; it < 4; it++) {
        int flat = it * 256 + tid;
        int r = flat >> 3, cc = flat & 7;
        size_t so = kv + (size_t)(qr0 + r) * DA + cc * 8;
        int off = r * 128 + ((cc ^ (r & 7)) << 4);
        cpa16(sm[0] + off, g_q + so);
    }
    cp_commit();
    cp_wait<0>();
    __syncthreads();

    unsigned qf[4][4];
    {
        int qrow = mw + ((grp & 1) << 3) + li;
        int q7 = qrow & 7;
#pragma unroll
        for (int s4 = 0; s4 < 4; s4++) {
            int sw = (((s4 * 2 + (grp >> 1)) ^ q7) << 4);
            ldsm4(qf[s4][0], qf[s4][1], qf[s4][2], qf[s4][3], sm[0] + qrow * 128 + sw);
        }
    }
    __syncthreads();

    int pr = tid >> 3, pc = tid & 7;
    int poff = pr * 128 + ((pc ^ (pr & 7)) << 4);

    auto load_stage = [&](char* S, int kt) {
        size_t so = kv + (size_t)(kt * 32 + pr) * DA + pc * 8;
        cpa16(S + poff,        g_k + so);
        cpa16(S + 4096 + poff, g_v + so);
#pragma unroll
        for (int it = 0; it < 4; it++) {
            int flat = it * 256 + tid;
            int r = flat >> 3, cc = flat & 7;
            cpa16(S + 8192 + r * 128 + ((cc ^ (r & 7)) << 4),
                  Bblk + (size_t)r * THW + kt * 32 + cc * 4);
        }
        cp_commit();
    };

    load_stage(sm[0], kt0);

    float m0 = -1e30f, m1 = -1e30f, l0 = 0.f, l1 = 0.f;
    float O[8][4] = {};

    const unsigned* mrow0 = g_mb + (qr0 + mw + g) * 32;
    const unsigned* mrow1 = mrow0 + 8 * 32;
    int brow0 = mw + g, brow1 = brow0 + 8;
    int boff = 8 * (tg & 1);
    int bch  = tg >> 1;

    for (int it16 = 0; it16 < 16; it16++) {
        int kt = kt0 + it16;
        unsigned mk0 = mrow0[kt];
        unsigned mk1 = mrow1[kt];
        if (it16 < 15) {
            load_stage(sm[(it16 + 1) & 1], kt + 1);
            cp_wait<1>();
        } else {
            cp_wait<0>();
        }
        __syncthreads();
        char* S = sm[it16 & 1];

        // ---- S = Q K^T (log2 domain), 32 kcols -> sc[4][4] ----
        float sc[4][4] = {};
#pragma unroll
        for (int s4 = 0; s4 < 4; s4++) {
#pragma unroll
            for (int jp = 0; jp < 2; jp++) {
                int rr = jp * 16 + ((grp >> 1) << 3) + li;
                int sw = (((s4 * 2 + (grp & 1)) ^ (rr & 7)) << 4);
                unsigned k0, k1, k2, k3;
                ldsm4(k0, k1, k2, k3, S + rr * 128 + sw);
                mma4(sc[2*jp],   qf[s4], k0, k1);
                mma4(sc[2*jp+1], qf[s4], k2, k3);
            }
        }

        // ---- bias (smem, FMA by LOG2E) + mask (bitmask -> -14427) ----
        char* Bs = S + 8192;
#pragma unroll
        for (int j = 0; j < 4; j++) {
            int ch = bch + 2 * j;
            float2 b0 = *(const float2*)(Bs + brow0 * 128 + (((ch ^ (brow0 & 7))) << 4) + boff);
            float2 b1 = *(const float2*)(Bs + brow1 * 128 + (((ch ^ (brow1 & 7))) << 4) + boff);
            int bit = 8 * j + 2 * tg;
            sc[j][0] = (mk0 >> bit)       & 1 ? -14427.f : fmaf(b0.x, LOG2E, sc[j][0]);
            sc[j][1] = (mk0 >> (bit + 1)) & 1 ? -14427.f : fmaf(b0.y, LOG2E, sc[j][1]);
            sc[j][2] = (mk1 >> bit)       & 1 ? -14427.f : fmaf(b1.x, LOG2E, sc[j][2]);
            sc[j][3] = (mk1 >> (bit + 1)) & 1 ? -14427.f : fmaf(b1.y, LOG2E, sc[j][3]);
        }

        // ---- online softmax (base-2) ----
        float rm0 = -1e30f, rm1 = -1e30f;
#pragma unroll
        for (int j = 0; j < 4; j++) {
            rm0 = fmaxf(rm0, fmaxf(sc[j][0], sc[j][1]));
            rm1 = fmaxf(rm1, fmaxf(sc[j][2], sc[j][3]));
        }
        rm0 = fmaxf(rm0, __shfl_xor_sync(0xffffffffu, rm0, 1));
        rm0 = fmaxf(rm0, __shfl_xor_sync(0xffffffffu, rm0, 2));
        rm1 = fmaxf(rm1, __shfl_xor_sync(0xffffffffu, rm1, 1));
        rm1 = fmaxf(rm1, __shfl_xor_sync(0xffffffffu, rm1, 2));
        float nm0 = fmaxf(m0, rm0), nm1 = fmaxf(m1, rm1);

        float ls0 = 0.f, ls1 = 0.f;
#pragma unroll
        for (int j = 0; j < 4; j++) {
            sc[j][0] = ex2f(sc[j][0] - nm0); ls0 += sc[j][0];
            sc[j][1] = ex2f(sc[j][1] - nm0); ls0 += sc[j][1];
            sc[j][2] = ex2f(sc[j][2] - nm1); ls1 += sc[j][2];
            sc[j][3] = ex2f(sc[j][3] - nm1); ls1 += sc[j][3];
        }
        ls0 += __shfl_xor_sync(0xffffffffu, ls0, 1);
        ls0 += __shfl_xor_sync(0xffffffffu, ls0, 2);
        ls1 += __shfl_xor_sync(0xffffffffu, ls1, 1);
        ls1 += __shfl_xor_sync(0xffffffffu, ls1, 2);

        bool nochange = (nm0 == m0) && (nm1 == m1);
        if (__all_sync(0xffffffffu, nochange)) {
            l0 += ls0;
            l1 += ls1;
        } else {
            float a0 = ex2f(m0 - nm0), a1 = ex2f(m1 - nm1);
            l0 = l0 * a0 + ls0;
            l1 = l1 * a1 + ls1;
            m0 = nm0; m1 = nm1;
#pragma unroll
            for (int j = 0; j < 8; j++) {
                O[j][0] *= a0; O[j][1] *= a0;
                O[j][2] *= a1; O[j][3] *= a1;
            }
        }

        // ---- O += P V ----
#pragma unroll
        for (int t = 0; t < 2; t++) {
            unsigned ph[4];
            ph[0] = pack2(sc[2*t][0],   sc[2*t][1]);
            ph[1] = pack2(sc[2*t][2],   sc[2*t][3]);
            ph[2] = pack2(sc[2*t+1][0], sc[2*t+1][1]);
            ph[3] = pack2(sc[2*t+1][2], sc[2*t+1][3]);
            int rr = 16 * t + ((grp & 1) << 3) + li;
            int r7 = rr & 7;
#pragma unroll
            for (int jp = 0; jp < 4; jp++) {
                int sw = (((2 * jp + (grp >> 1)) ^ r7) << 4);
                unsigned v0, v1, v2, v3;
                ldsm4t(v0, v1, v2, v3, S + 4096 + rr * 128 + sw);
                mma4(O[2*jp],   ph, v0, v1);
                mma4(O[2*jp+1], ph, v2, v3);
            }
        }
        __syncthreads();
    }

    // ---- write partial (unnormalized O fp32 + m,l) ----
    int tok0 = b * THW + qr0 + mw + g;
    if (tg == 0) {
        g_pml[ks][h][tok0][0]     = m0;
        g_pml[ks][h][tok0][1]     = l0;
        g_pml[ks][h][tok0 + 8][0] = m1;
        g_pml[ks][h][tok0 + 8][1] = l1;
    }
#pragma unroll
    for (int j = 0; j < 8; j++) {
        int col = h * DA + j * 8 + 2 * tg;
        *(float2*)&g_pO[ks][(size_t)tok0 * DD + col]       = make_float2(O[j][0], O[j][1]);
        *(float2*)&g_pO[ks][(size_t)(tok0 + 8) * DD + col] = make_float2(O[j][2], O[j][3]);
    }
}

// ---------------------------------------------------------------- split-KV combine
// grid 4096 (one block per token), 256 thr (2 cols each)
__global__ void combine_k() {
    int tok = blockIdx.x;
    int t = threadIdx.x;
    int h = t >> 5;                       // cols 2t,2t+1 belong to head t/32
    float m0 = g_pml[0][h][tok][0], l0 = g_pml[0][h][tok][1];
    float m1 = g_pml[1][h][tok][0], l1 = g_pml[1][h][tok][1];
    float m = fmaxf(m0, m1);
    float w0 = ex2f(m0 - m), w1 = ex2f(m1 - m);
    float inv = 1.f / (l0 * w0 + l1 * w1);
    size_t off = (size_t)tok * DD + 2 * t;
    float2 a = *(const float2*)&g_pO[0][off];
    float2 c = *(const float2*)&g_pO[1][off];
    *(unsigned*)(g_ao + off) = pack2((a.x * w0 + c.x * w1) * inv,
                                     (a.y * w0 + c.y * w1) * inv);
}

// ---------------------------------------------------------------- launch
extern "C" void kernel_launch(void* const* d_in, const int* in_sizes, int n_in,
                              void* d_out, int out_size) {
    const float* x     = (const float*)d_in[0];
    const float* Bb    = (const float*)d_in[1];
    const int*   M     = (const int*)  d_in[2];
    const float* gamma = (const float*)d_in[3];
    const float* beta  = (const float*)d_in[4];
    const float* wq    = (const float*)d_in[5];
    const float* wk    = (const float*)d_in[6];
    const float* wv    = (const float*)d_in[7];
    const float* wp    = (const float*)d_in[8];
    float* out = (float*)d_out;

    cudaFuncSetAttribute(qkv_g,  cudaFuncAttributeMaxDynamicSharedMemorySize, 3 * STG);
    cudaFuncSetAttribute(proj_g, cudaFuncAttributeMaxDynamicSharedMemorySize, 3 * STG);

    ln_kernel<<<NROWS, 128>>>(x, gamma, beta);
    prep_all<<<PW_BLKS + PWP_BLKS + 4096, 256>>>(wq, wk, wv, wp, M);
    qkv_g<<<dim3(NROWS / 128, NQKV / 128), 256, 3 * STG>>>();
    attn_kernel<<<dim3(8, NA * BSZ, 2), 256>>>(Bb);
    combine_k<<<NROWS, 256>>>();
    proj_g<<<dim3(NROWS / 128, DD / 128), 256, 3 * STG>>>(x, out);
}